// round 1
// baseline (speedup 1.0000x reference)
#include <cuda_runtime.h>

// Problem dims (fixed by the reference).
#define BB 1024   // batch
#define DD 512    // latent dim
#define HH 1024   // MLP hidden
#define TT 64     // time points

// Persistent state (scratch) — __device__ globals per the allocation rules.
__device__ float g_z  [BB * DD];   // current z
__device__ float g_zin[BB * DD];   // stage input
__device__ float g_acc[BB * DD];   // k1 + 2k2 + 2k3 accumulator
__device__ float g_h  [BB * HH];   // hidden activation tanh(zin@W1+b1)

__global__ void init_kernel(const float* __restrict__ z0, float* __restrict__ traj) {
    int i = blockIdx.x * blockDim.x + threadIdx.x;
    if (i < BB * DD) {
        float v = z0[i];
        g_z[i]   = v;
        g_zin[i] = v;
        traj[i]  = v;   // traj[0] = z0
    }
}

// ---------------------------------------------------------------------------
// GEMM 1: g_h[B,H] = tanh(g_zin[B,D] @ W1[D,H] + b1)
// 64x64 block tile, TK=16, 256 threads, 4x4 per thread.
// ---------------------------------------------------------------------------
__global__ void __launch_bounds__(256) gemm1_tanh(const float* __restrict__ W1,
                                                  const float* __restrict__ b1) {
    __shared__ float As[16][64];   // [k][m]
    __shared__ float Bs[16][64];   // [k][n]

    const int tx = threadIdx.x;          // 0..15 -> N
    const int ty = threadIdx.y;          // 0..15 -> M
    const int tid = ty * 16 + tx;
    const int m0 = blockIdx.y * 64;
    const int n0 = blockIdx.x * 64;

    // load assignments (4 consecutive floats per thread, vectorized)
    const int ar = (tid * 4) / 16, ac = (tid * 4) % 16;   // A tile 64x16
    const int br = (tid * 4) / 64, bc = (tid * 4) % 64;   // B tile 16x64

    float acc[4][4] = {};

    for (int kk = 0; kk < DD; kk += 16) {
        float4 av = *(const float4*)&g_zin[(m0 + ar) * DD + kk + ac];
        float4 bv = *(const float4*)&W1[(size_t)(kk + br) * HH + n0 + bc];
        __syncthreads();   // previous tile fully consumed
        As[ac + 0][ar] = av.x;
        As[ac + 1][ar] = av.y;
        As[ac + 2][ar] = av.z;
        As[ac + 3][ar] = av.w;
        *(float4*)&Bs[br][bc] = bv;
        __syncthreads();   // tile ready

        #pragma unroll
        for (int k = 0; k < 16; k++) {
            float a[4], b[4];
            #pragma unroll
            for (int i = 0; i < 4; i++) a[i] = As[k][ty * 4 + i];
            #pragma unroll
            for (int j = 0; j < 4; j++) b[j] = Bs[k][tx * 4 + j];
            #pragma unroll
            for (int i = 0; i < 4; i++)
                #pragma unroll
                for (int j = 0; j < 4; j++)
                    acc[i][j] = fmaf(a[i], b[j], acc[i][j]);
        }
    }

    #pragma unroll
    for (int i = 0; i < 4; i++) {
        int m = m0 + ty * 4 + i;
        #pragma unroll
        for (int j = 0; j < 4; j++) {
            int n = n0 + tx * 4 + j;
            g_h[(size_t)m * HH + n] = tanhf(acc[i][j] + b1[n]);
        }
    }
}

// ---------------------------------------------------------------------------
// GEMM 2 + RK4 combine: k = g_h[B,H] @ W2[H,D] + b2, then per-stage update.
//   stage 0: acc = k;        zin = z + 0.5*dt*k
//   stage 1: acc += 2k;      zin = z + 0.5*dt*k
//   stage 2: acc += 2k;      zin = z + dt*k
//   stage 3: z' = z + dt/6*(acc + k); z=zin=z'; traj[step+1]=z'
// ---------------------------------------------------------------------------
__global__ void __launch_bounds__(256) gemm2_combine(const float* __restrict__ W2,
                                                     const float* __restrict__ b2,
                                                     const float* __restrict__ t,
                                                     int step, int stage,
                                                     float* __restrict__ traj) {
    __shared__ float As[16][64];
    __shared__ float Bs[16][64];

    const int tx = threadIdx.x;
    const int ty = threadIdx.y;
    const int tid = ty * 16 + tx;
    const int m0 = blockIdx.y * 64;
    const int n0 = blockIdx.x * 64;

    const int ar = (tid * 4) / 16, ac = (tid * 4) % 16;
    const int br = (tid * 4) / 64, bc = (tid * 4) % 64;

    float acc[4][4] = {};

    for (int kk = 0; kk < HH; kk += 16) {
        float4 av = *(const float4*)&g_h[(size_t)(m0 + ar) * HH + kk + ac];
        float4 bv = *(const float4*)&W2[(size_t)(kk + br) * DD + n0 + bc];
        __syncthreads();
        As[ac + 0][ar] = av.x;
        As[ac + 1][ar] = av.y;
        As[ac + 2][ar] = av.z;
        As[ac + 3][ar] = av.w;
        *(float4*)&Bs[br][bc] = bv;
        __syncthreads();

        #pragma unroll
        for (int k = 0; k < 16; k++) {
            float a[4], b[4];
            #pragma unroll
            for (int i = 0; i < 4; i++) a[i] = As[k][ty * 4 + i];
            #pragma unroll
            for (int j = 0; j < 4; j++) b[j] = Bs[k][tx * 4 + j];
            #pragma unroll
            for (int i = 0; i < 4; i++)
                #pragma unroll
                for (int j = 0; j < 4; j++)
                    acc[i][j] = fmaf(a[i], b[j], acc[i][j]);
        }
    }

    const float dt = t[step + 1] - t[step];

    #pragma unroll
    for (int i = 0; i < 4; i++) {
        int m = m0 + ty * 4 + i;
        #pragma unroll
        for (int j = 0; j < 4; j++) {
            int n = n0 + tx * 4 + j;
            int idx = m * DD + n;
            float kv = acc[i][j] + b2[n];
            float zv = g_z[idx];
            if (stage == 0) {
                g_acc[idx] = kv;
                g_zin[idx] = zv + 0.5f * dt * kv;
            } else if (stage == 1) {
                g_acc[idx] += 2.0f * kv;
                g_zin[idx] = zv + 0.5f * dt * kv;
            } else if (stage == 2) {
                g_acc[idx] += 2.0f * kv;
                g_zin[idx] = zv + dt * kv;
            } else {
                float zn = zv + (dt * (1.0f / 6.0f)) * (g_acc[idx] + kv);
                g_z[idx]   = zn;
                g_zin[idx] = zn;
                traj[(size_t)(step + 1) * BB * DD + idx] = zn;
            }
        }
    }
}

extern "C" void kernel_launch(void* const* d_in, const int* in_sizes, int n_in,
                              void* d_out, int out_size) {
    const float* z0 = (const float*)d_in[0];
    const float* t  = (const float*)d_in[1];
    const float* W1 = (const float*)d_in[2];
    const float* b1 = (const float*)d_in[3];
    const float* W2 = (const float*)d_in[4];
    const float* b2 = (const float*)d_in[5];
    float* traj = (float*)d_out;

    init_kernel<<<(BB * DD + 255) / 256, 256>>>(z0, traj);

    dim3 thr(16, 16);
    dim3 grid1(HH / 64, BB / 64);   // 16 x 16 blocks
    dim3 grid2(DD / 64, BB / 64);   // 8  x 16 blocks

    for (int step = 0; step < TT - 1; step++) {
        for (int s = 0; s < 4; s++) {
            gemm1_tanh<<<grid1, thr>>>(W1, b1);
            gemm2_combine<<<grid2, thr>>>(W2, b2, t, step, s, traj);
        }
    }
}

// round 2
// speedup vs baseline: 2.4839x; 2.4839x over previous
#include <cuda_runtime.h>
#include <cuda_bf16.h>
#include <cstdint>

#define BB 1024   // batch
#define DD 512    // latent dim
#define HH 1024   // MLP hidden
#define TT 64     // time points

// ---------------------------------------------------------------------------
// Persistent device state (no allocs allowed).
// ---------------------------------------------------------------------------
__device__ float g_z  [BB * DD];            // current z (fp32)
__device__ float g_acc[BB * DD];            // k1 + 2k2 + 2k3 accumulator
__device__ __nv_bfloat16 g_zihi[BB * DD];   // stage input hi
__device__ __nv_bfloat16 g_zilo[BB * DD];   // stage input lo
__device__ __nv_bfloat16 g_hhi [BB * HH];   // hidden activation hi
__device__ __nv_bfloat16 g_hlo [BB * HH];   // hidden activation lo
__device__ __nv_bfloat16 g_W1hi[DD * HH];
__device__ __nv_bfloat16 g_W1lo[DD * HH];
__device__ __nv_bfloat16 g_W2hi[HH * DD];
__device__ __nv_bfloat16 g_W2lo[HH * DD];

// ---------------------------------------------------------------------------
// PTX helpers
// ---------------------------------------------------------------------------
__device__ __forceinline__ void cpa16(void* dst, const void* src) {
    uint32_t d = (uint32_t)__cvta_generic_to_shared(dst);
    asm volatile("cp.async.cg.shared.global [%0], [%1], 16;\n" :: "r"(d), "l"(src));
}
__device__ __forceinline__ void cp_commit() {
    asm volatile("cp.async.commit_group;\n" ::: "memory");
}
__device__ __forceinline__ void cp_wait0() {
    asm volatile("cp.async.wait_group 0;\n" ::: "memory");
}
__device__ __forceinline__ void ldsm4(uint32_t* r, const __nv_bfloat16* p) {
    uint32_t a = (uint32_t)__cvta_generic_to_shared(p);
    asm volatile("ldmatrix.sync.aligned.m8n8.x4.shared.b16 {%0,%1,%2,%3},[%4];\n"
                 : "=r"(r[0]), "=r"(r[1]), "=r"(r[2]), "=r"(r[3]) : "r"(a));
}
__device__ __forceinline__ void ldsm4t(uint32_t* r, const __nv_bfloat16* p) {
    uint32_t a = (uint32_t)__cvta_generic_to_shared(p);
    asm volatile("ldmatrix.sync.aligned.m8n8.x4.trans.shared.b16 {%0,%1,%2,%3},[%4];\n"
                 : "=r"(r[0]), "=r"(r[1]), "=r"(r[2]), "=r"(r[3]) : "r"(a));
}
__device__ __forceinline__ void mma_bf16(float* c, const uint32_t* a, uint32_t b0, uint32_t b1) {
    asm volatile("mma.sync.aligned.m16n8k16.row.col.f32.bf16.bf16.f32 "
                 "{%0,%1,%2,%3}, {%4,%5,%6,%7}, {%8,%9}, {%0,%1,%2,%3};\n"
                 : "+f"(c[0]), "+f"(c[1]), "+f"(c[2]), "+f"(c[3])
                 : "r"(a[0]), "r"(a[1]), "r"(a[2]), "r"(a[3]), "r"(b0), "r"(b1));
}

// ---------------------------------------------------------------------------
// Mainloop: 64x64 CTA tile, BK=32, bf16x3 split products, fp32 accumulate.
// A: [M,KDIM] row-major bf16 (hi/lo).  B: [KDIM,NDIM] row-major bf16 (hi/lo).
// 128 threads; warps 2x2; warp tile 32x32; mma m16n8k16.
// ---------------------------------------------------------------------------
template <int KDIM, int NDIM>
__device__ __forceinline__ void mainloop(
    const __nv_bfloat16* __restrict__ Ahi, const __nv_bfloat16* __restrict__ Alo,
    const __nv_bfloat16* __restrict__ Bhi, const __nv_bfloat16* __restrict__ Blo,
    int m0, int n0, float c[2][4][4])
{
    __shared__ __align__(16) __nv_bfloat16 sA[2][2][64 * 40];  // [buf][hi/lo][m*40+k]
    __shared__ __align__(16) __nv_bfloat16 sB[2][2][32 * 72];  // [buf][hi/lo][k*72+n]

    const int tid  = threadIdx.x;
    const int wid  = tid >> 5;
    const int lane = tid & 31;
    const int wm = (wid >> 1) * 32;
    const int wn = (wid & 1) * 32;
    const int lr  = lane & 15;
    const int lc8 = (lane >> 4) * 8;

    auto load_tile = [&](int it, int b) {
        const int kk = it * 32;
#pragma unroll
        for (int i = 0; i < 2; i++) {
            int ch = tid + i * 128;                   // 0..255
            int r  = ch >> 2, cA = (ch & 3) * 8;      // A: 64 rows x 4 chunks
            size_t ga = (size_t)(m0 + r) * KDIM + kk + cA;
            cpa16(&sA[b][0][r * 40 + cA], Ahi + ga);
            cpa16(&sA[b][1][r * 40 + cA], Alo + ga);
            int rb = ch >> 3, cB = (ch & 7) * 8;      // B: 32 rows x 8 chunks
            size_t gb = (size_t)(kk + rb) * NDIM + n0 + cB;
            cpa16(&sB[b][0][rb * 72 + cB], Bhi + gb);
            cpa16(&sB[b][1][rb * 72 + cB], Blo + gb);
        }
        cp_commit();
    };

    auto compute = [&](int b) {
#pragma unroll
        for (int s = 0; s < 2; s++) {
            uint32_t ah[2][4], al[2][4];
#pragma unroll
            for (int mt = 0; mt < 2; mt++) {
                int off = (wm + mt * 16 + lr) * 40 + s * 16 + lc8;
                ldsm4(ah[mt], &sA[b][0][off]);
                ldsm4(al[mt], &sA[b][1][off]);
            }
            uint32_t bh[2][4], bl[2][4];
#pragma unroll
            for (int g = 0; g < 2; g++) {
                int off = (s * 16 + lr) * 72 + wn + g * 16 + lc8;
                ldsm4t(bh[g], &sB[b][0][off]);
                ldsm4t(bl[g], &sB[b][1][off]);
            }
#pragma unroll
            for (int mt = 0; mt < 2; mt++)
#pragma unroll
                for (int nt = 0; nt < 4; nt++) {
                    int g = nt >> 1, w = (nt & 1) * 2;
                    mma_bf16(c[mt][nt], ah[mt], bh[g][w], bh[g][w + 1]);
                    mma_bf16(c[mt][nt], ah[mt], bl[g][w], bl[g][w + 1]);
                    mma_bf16(c[mt][nt], al[mt], bh[g][w], bh[g][w + 1]);
                }
        }
    };

    constexpr int NT = KDIM / 32;
    load_tile(0, 0);
    int buf = 0;
#pragma unroll 1
    for (int it = 0; it < NT; it++) {
        cp_wait0();
        __syncthreads();
        if (it + 1 < NT) load_tile(it + 1, buf ^ 1);
        compute(buf);
        buf ^= 1;
    }
}

// ---------------------------------------------------------------------------
// GEMM1: h = tanh(zin @ W1 + b1)  ->  g_hhi/g_hlo
// ---------------------------------------------------------------------------
__global__ void __launch_bounds__(128) k_gemm1(const float* __restrict__ b1) {
    const int m0 = blockIdx.y * 64, n0 = blockIdx.x * 64;
    float c[2][4][4] = {};
    mainloop<DD, HH>(g_zihi, g_zilo, g_W1hi, g_W1lo, m0, n0, c);

    const int wid = threadIdx.x >> 5, lane = threadIdx.x & 31;
    const int wm = (wid >> 1) * 32, wn = (wid & 1) * 32;
    const int er = lane >> 2, ec = (lane & 3) * 2;
#pragma unroll
    for (int mt = 0; mt < 2; mt++)
#pragma unroll
        for (int nt = 0; nt < 4; nt++) {
            int gn = n0 + wn + nt * 8 + ec;
            float bv0 = b1[gn], bv1 = b1[gn + 1];
#pragma unroll
            for (int h = 0; h < 2; h++) {
                int gm = m0 + wm + mt * 16 + er + h * 8;
                float v0 = tanhf(c[mt][nt][2 * h + 0] + bv0);
                float v1 = tanhf(c[mt][nt][2 * h + 1] + bv1);
                __nv_bfloat16 h0 = __float2bfloat16(v0);
                __nv_bfloat16 h1 = __float2bfloat16(v1);
                __nv_bfloat16 l0 = __float2bfloat16(v0 - __bfloat162float(h0));
                __nv_bfloat16 l1 = __float2bfloat16(v1 - __bfloat162float(h1));
                size_t idx = (size_t)gm * HH + gn;
                *reinterpret_cast<__nv_bfloat162*>(&g_hhi[idx]) = __halves2bfloat162(h0, h1);
                *reinterpret_cast<__nv_bfloat162*>(&g_hlo[idx]) = __halves2bfloat162(l0, l1);
            }
        }
}

// ---------------------------------------------------------------------------
// GEMM2 + RK4 combine: k = h @ W2 + b2, then stage update.
// ---------------------------------------------------------------------------
__global__ void __launch_bounds__(128) k_gemm2(const float* __restrict__ b2,
                                               const float* __restrict__ t,
                                               int step, int stage,
                                               float* __restrict__ traj) {
    const int m0 = blockIdx.y * 64, n0 = blockIdx.x * 64;
    float c[2][4][4] = {};
    mainloop<HH, DD>(g_hhi, g_hlo, g_W2hi, g_W2lo, m0, n0, c);

    const float dt = t[step + 1] - t[step];
    const int wid = threadIdx.x >> 5, lane = threadIdx.x & 31;
    const int wm = (wid >> 1) * 32, wn = (wid & 1) * 32;
    const int er = lane >> 2, ec = (lane & 3) * 2;

#pragma unroll
    for (int mt = 0; mt < 2; mt++)
#pragma unroll
        for (int nt = 0; nt < 4; nt++) {
            int gn = n0 + wn + nt * 8 + ec;
            float bv0 = b2[gn], bv1 = b2[gn + 1];
#pragma unroll
            for (int h = 0; h < 2; h++) {
                int gm = m0 + wm + mt * 16 + er + h * 8;
                int idx = gm * DD + gn;
                float k0 = c[mt][nt][2 * h + 0] + bv0;
                float k1 = c[mt][nt][2 * h + 1] + bv1;
                float2 zv = *reinterpret_cast<const float2*>(&g_z[idx]);
                float zi0, zi1;
                if (stage == 0) {
                    *reinterpret_cast<float2*>(&g_acc[idx]) = make_float2(k0, k1);
                    zi0 = zv.x + 0.5f * dt * k0;
                    zi1 = zv.y + 0.5f * dt * k1;
                } else if (stage == 1) {
                    float2 a = *reinterpret_cast<const float2*>(&g_acc[idx]);
                    *reinterpret_cast<float2*>(&g_acc[idx]) =
                        make_float2(a.x + 2.f * k0, a.y + 2.f * k1);
                    zi0 = zv.x + 0.5f * dt * k0;
                    zi1 = zv.y + 0.5f * dt * k1;
                } else if (stage == 2) {
                    float2 a = *reinterpret_cast<const float2*>(&g_acc[idx]);
                    *reinterpret_cast<float2*>(&g_acc[idx]) =
                        make_float2(a.x + 2.f * k0, a.y + 2.f * k1);
                    zi0 = zv.x + dt * k0;
                    zi1 = zv.y + dt * k1;
                } else {
                    float2 a = *reinterpret_cast<const float2*>(&g_acc[idx]);
                    zi0 = zv.x + (dt * (1.0f / 6.0f)) * (a.x + k0);
                    zi1 = zv.y + (dt * (1.0f / 6.0f)) * (a.y + k1);
                    *reinterpret_cast<float2*>(&g_z[idx]) = make_float2(zi0, zi1);
                    *reinterpret_cast<float2*>(&traj[(size_t)(step + 1) * BB * DD + idx]) =
                        make_float2(zi0, zi1);
                }
                __nv_bfloat16 h0 = __float2bfloat16(zi0);
                __nv_bfloat16 h1 = __float2bfloat16(zi1);
                __nv_bfloat16 l0 = __float2bfloat16(zi0 - __bfloat162float(h0));
                __nv_bfloat16 l1 = __float2bfloat16(zi1 - __bfloat162float(h1));
                *reinterpret_cast<__nv_bfloat162*>(&g_zihi[idx]) = __halves2bfloat162(h0, h1);
                *reinterpret_cast<__nv_bfloat162*>(&g_zilo[idx]) = __halves2bfloat162(l0, l1);
            }
        }
}

// ---------------------------------------------------------------------------
// Setup kernels
// ---------------------------------------------------------------------------
__global__ void split_kernel(const float* __restrict__ src,
                             __nv_bfloat16* __restrict__ hi,
                             __nv_bfloat16* __restrict__ lo, int n) {
    int i = blockIdx.x * 256 + threadIdx.x;
    if (i < n) {
        float v = src[i];
        __nv_bfloat16 h = __float2bfloat16(v);
        hi[i] = h;
        lo[i] = __float2bfloat16(v - __bfloat162float(h));
    }
}

__global__ void init_kernel(const float* __restrict__ z0, float* __restrict__ traj) {
    int i = blockIdx.x * 256 + threadIdx.x;
    if (i < BB * DD) {
        float v = z0[i];
        g_z[i]  = v;
        traj[i] = v;
        __nv_bfloat16 h = __float2bfloat16(v);
        g_zihi[i] = h;
        g_zilo[i] = __float2bfloat16(v - __bfloat162float(h));
    }
}

// ---------------------------------------------------------------------------
extern "C" void kernel_launch(void* const* d_in, const int* in_sizes, int n_in,
                              void* d_out, int out_size) {
    const float* z0 = (const float*)d_in[0];
    const float* t  = (const float*)d_in[1];
    const float* W1 = (const float*)d_in[2];
    const float* b1 = (const float*)d_in[3];
    const float* W2 = (const float*)d_in[4];
    const float* b2 = (const float*)d_in[5];
    float* traj = (float*)d_out;

    __nv_bfloat16 *w1hi, *w1lo, *w2hi, *w2lo;
    cudaGetSymbolAddress((void**)&w1hi, g_W1hi);
    cudaGetSymbolAddress((void**)&w1lo, g_W1lo);
    cudaGetSymbolAddress((void**)&w2hi, g_W2hi);
    cudaGetSymbolAddress((void**)&w2lo, g_W2lo);

    split_kernel<<<(DD * HH + 255) / 256, 256>>>(W1, w1hi, w1lo, DD * HH);
    split_kernel<<<(HH * DD + 255) / 256, 256>>>(W2, w2hi, w2lo, HH * DD);
    init_kernel<<<(BB * DD + 255) / 256, 256>>>(z0, traj);

    dim3 thr(128);
    dim3 grid1(HH / 64, BB / 64);   // 16 x 16
    dim3 grid2(DD / 64, BB / 64);   // 8  x 16

    for (int step = 0; step < TT - 1; step++) {
        for (int s = 0; s < 4; s++) {
            k_gemm1<<<grid1, thr>>>(b1);
            k_gemm2<<<grid2, thr>>>(b2, t, step, s, traj);
        }
    }
}

// round 3
// speedup vs baseline: 2.7151x; 1.0931x over previous
#include <cuda_runtime.h>
#include <cuda_bf16.h>
#include <cstdint>

#define BB 1024   // batch
#define DD 512    // latent dim
#define HH 1024   // MLP hidden
#define TT 64     // time points

// ---------------------------------------------------------------------------
// Persistent device state (no allocs allowed).
// ---------------------------------------------------------------------------
__device__ float g_z  [BB * DD];            // current z (fp32)
__device__ float g_acc[BB * DD];            // k1 + 2k2 + 2k3 accumulator
__device__ __nv_bfloat16 g_zihi[BB * DD];   // stage input hi
__device__ __nv_bfloat16 g_zilo[BB * DD];   // stage input lo
__device__ __nv_bfloat16 g_hhi [BB * HH];   // hidden activation hi
__device__ __nv_bfloat16 g_hlo [BB * HH];   // hidden activation lo
__device__ __nv_bfloat16 g_W1hi[DD * HH];
__device__ __nv_bfloat16 g_W1lo[DD * HH];
__device__ __nv_bfloat16 g_W2hi[HH * DD];
__device__ __nv_bfloat16 g_W2lo[HH * DD];

// SMEM layout (dynamic): 3-stage double-split tiles.
//   sA[3][2][64*40]  : A tiles (hi/lo), row stride 40 bf16 (80 B)
//   sB[3][2][32*72]  : B tiles (hi/lo), row stride 72 bf16 (144 B)
#define SA_STRIDE 2560          // 64*40 elems per (buf,split)
#define SB_STRIDE 2304          // 32*72 elems per (buf,split)
#define SB_BASE   (3 * 2 * SA_STRIDE)
#define SMEM_ELEMS (SB_BASE + 3 * 2 * SB_STRIDE)
#define SMEM_BYTES (SMEM_ELEMS * 2)   // 58368

// ---------------------------------------------------------------------------
// PTX helpers
// ---------------------------------------------------------------------------
__device__ __forceinline__ void cpa16(void* dst, const void* src) {
    uint32_t d = (uint32_t)__cvta_generic_to_shared(dst);
    asm volatile("cp.async.cg.shared.global [%0], [%1], 16;\n" :: "r"(d), "l"(src));
}
__device__ __forceinline__ void cp_commit() {
    asm volatile("cp.async.commit_group;\n" ::: "memory");
}
__device__ __forceinline__ void cp_wait1() {
    asm volatile("cp.async.wait_group 1;\n" ::: "memory");
}
__device__ __forceinline__ void ldsm4(uint32_t* r, const __nv_bfloat16* p) {
    uint32_t a = (uint32_t)__cvta_generic_to_shared(p);
    asm volatile("ldmatrix.sync.aligned.m8n8.x4.shared.b16 {%0,%1,%2,%3},[%4];\n"
                 : "=r"(r[0]), "=r"(r[1]), "=r"(r[2]), "=r"(r[3]) : "r"(a));
}
__device__ __forceinline__ void ldsm4t(uint32_t* r, const __nv_bfloat16* p) {
    uint32_t a = (uint32_t)__cvta_generic_to_shared(p);
    asm volatile("ldmatrix.sync.aligned.m8n8.x4.trans.shared.b16 {%0,%1,%2,%3},[%4];\n"
                 : "=r"(r[0]), "=r"(r[1]), "=r"(r[2]), "=r"(r[3]) : "r"(a));
}
__device__ __forceinline__ void mma_bf16(float* c, const uint32_t* a, uint32_t b0, uint32_t b1) {
    asm volatile("mma.sync.aligned.m16n8k16.row.col.f32.bf16.bf16.f32 "
                 "{%0,%1,%2,%3}, {%4,%5,%6,%7}, {%8,%9}, {%0,%1,%2,%3};\n"
                 : "+f"(c[0]), "+f"(c[1]), "+f"(c[2]), "+f"(c[3])
                 : "r"(a[0]), "r"(a[1]), "r"(a[2]), "r"(a[3]), "r"(b0), "r"(b1));
}

// ---------------------------------------------------------------------------
// Mainloop: 64x64 CTA tile, BK=32, 256 threads, 8 warps (4M x 2N),
// warp tile 16x32, bf16x3 split products, fp32 accumulate, 3-stage pipeline.
// A: [M,KDIM] row-major bf16 (hi/lo).  B: [KDIM,NDIM] row-major bf16 (hi/lo).
// ---------------------------------------------------------------------------
template <int KDIM, int NDIM>
__device__ __forceinline__ void mainloop(
    const __nv_bfloat16* __restrict__ Ahi, const __nv_bfloat16* __restrict__ Alo,
    const __nv_bfloat16* __restrict__ Bhi, const __nv_bfloat16* __restrict__ Blo,
    int m0, int n0, float c[4][4])
{
    extern __shared__ __align__(16) __nv_bfloat16 sm[];
    __nv_bfloat16* sA = sm;
    __nv_bfloat16* sB = sm + SB_BASE;

    const int tid  = threadIdx.x;
    const int wid  = tid >> 5;
    const int lane = tid & 31;
    const int wm = (wid >> 1) * 16;          // 4 warp-rows
    const int wn = (wid & 1) * 32;           // 2 warp-cols
    const int lr  = lane & 15;
    const int lc8 = (lane >> 4) * 8;

    // Load mapping: each thread moves one 16B chunk per split per matrix.
    const int ar  = tid >> 2, acol = (tid & 3) * 8;   // A: 64 rows x 4 chunks
    const int brr = tid >> 3, bcol = (tid & 7) * 8;   // B: 32 rows x 8 chunks

    auto load_tile = [&](int it, int b) {
        const int kk = it * 32;
        size_t ga = (size_t)(m0 + ar) * KDIM + kk + acol;
        cpa16(sA + (b * 2 + 0) * SA_STRIDE + ar * 40 + acol, Ahi + ga);
        cpa16(sA + (b * 2 + 1) * SA_STRIDE + ar * 40 + acol, Alo + ga);
        size_t gb = (size_t)(kk + brr) * NDIM + n0 + bcol;
        cpa16(sB + (b * 2 + 0) * SB_STRIDE + brr * 72 + bcol, Bhi + gb);
        cpa16(sB + (b * 2 + 1) * SB_STRIDE + brr * 72 + bcol, Blo + gb);
        cp_commit();
    };

    auto compute = [&](int b) {
#pragma unroll
        for (int s = 0; s < 2; s++) {
            uint32_t ah[4], al[4];
            const int aoff = (wm + lr) * 40 + s * 16 + lc8;
            ldsm4(ah, sA + (b * 2 + 0) * SA_STRIDE + aoff);
            ldsm4(al, sA + (b * 2 + 1) * SA_STRIDE + aoff);
            uint32_t bh[2][4], bl[2][4];
#pragma unroll
            for (int g = 0; g < 2; g++) {
                const int boff = (s * 16 + lr) * 72 + wn + g * 16 + lc8;
                ldsm4t(bh[g], sB + (b * 2 + 0) * SB_STRIDE + boff);
                ldsm4t(bl[g], sB + (b * 2 + 1) * SB_STRIDE + boff);
            }
#pragma unroll
            for (int nt = 0; nt < 4; nt++) {
                const int g = nt >> 1, w = (nt & 1) * 2;
                mma_bf16(c[nt], ah, bh[g][w], bh[g][w + 1]);
                mma_bf16(c[nt], ah, bl[g][w], bl[g][w + 1]);
                mma_bf16(c[nt], al, bh[g][w], bh[g][w + 1]);
            }
        }
    };

    constexpr int NT = KDIM / 32;
    load_tile(0, 0);
    load_tile(1, 1);
#pragma unroll 1
    for (int it = 0; it < NT; it++) {
        const int b = it % 3;
        cp_wait1();          // tile `it` resident (<=1 group pending)
        __syncthreads();     // all threads done with buffer (it+2)%3 from iter it-1
        if (it + 2 < NT) load_tile(it + 2, (it + 2) % 3);
        compute(b);
    }
}

// ---------------------------------------------------------------------------
// GEMM1: h = tanh(zin @ W1 + b1)  ->  g_hhi/g_hlo
// ---------------------------------------------------------------------------
__global__ void __launch_bounds__(256) k_gemm1(const float* __restrict__ b1) {
    const int m0 = blockIdx.y * 64, n0 = blockIdx.x * 64;
    float c[4][4] = {};
    mainloop<DD, HH>(g_zihi, g_zilo, g_W1hi, g_W1lo, m0, n0, c);

    const int wid = threadIdx.x >> 5, lane = threadIdx.x & 31;
    const int wm = (wid >> 1) * 16, wn = (wid & 1) * 32;
    const int er = lane >> 2, ec = (lane & 3) * 2;
#pragma unroll
    for (int nt = 0; nt < 4; nt++) {
        int gn = n0 + wn + nt * 8 + ec;
        float bv0 = b1[gn], bv1 = b1[gn + 1];
#pragma unroll
        for (int h = 0; h < 2; h++) {
            int gm = m0 + wm + er + h * 8;
            float v0 = tanhf(c[nt][2 * h + 0] + bv0);
            float v1 = tanhf(c[nt][2 * h + 1] + bv1);
            __nv_bfloat16 h0 = __float2bfloat16(v0);
            __nv_bfloat16 h1 = __float2bfloat16(v1);
            __nv_bfloat16 l0 = __float2bfloat16(v0 - __bfloat162float(h0));
            __nv_bfloat16 l1 = __float2bfloat16(v1 - __bfloat162float(h1));
            size_t idx = (size_t)gm * HH + gn;
            *reinterpret_cast<__nv_bfloat162*>(&g_hhi[idx]) = __halves2bfloat162(h0, h1);
            *reinterpret_cast<__nv_bfloat162*>(&g_hlo[idx]) = __halves2bfloat162(l0, l1);
        }
    }
}

// ---------------------------------------------------------------------------
// GEMM2 + RK4 combine: k = h @ W2 + b2, then stage update.
// ---------------------------------------------------------------------------
__global__ void __launch_bounds__(256) k_gemm2(const float* __restrict__ b2,
                                               const float* __restrict__ t,
                                               int step, int stage,
                                               float* __restrict__ traj) {
    const int m0 = blockIdx.y * 64, n0 = blockIdx.x * 64;
    float c[4][4] = {};
    mainloop<HH, DD>(g_hhi, g_hlo, g_W2hi, g_W2lo, m0, n0, c);

    const float dt = t[step + 1] - t[step];
    const int wid = threadIdx.x >> 5, lane = threadIdx.x & 31;
    const int wm = (wid >> 1) * 16, wn = (wid & 1) * 32;
    const int er = lane >> 2, ec = (lane & 3) * 2;

#pragma unroll
    for (int nt = 0; nt < 4; nt++) {
        int gn = n0 + wn + nt * 8 + ec;
        float bv0 = b2[gn], bv1 = b2[gn + 1];
#pragma unroll
        for (int h = 0; h < 2; h++) {
            int gm = m0 + wm + er + h * 8;
            int idx = gm * DD + gn;
            float k0 = c[nt][2 * h + 0] + bv0;
            float k1 = c[nt][2 * h + 1] + bv1;
            float2 zv = *reinterpret_cast<const float2*>(&g_z[idx]);
            float zi0, zi1;
            if (stage == 0) {
                *reinterpret_cast<float2*>(&g_acc[idx]) = make_float2(k0, k1);
                zi0 = zv.x + 0.5f * dt * k0;
                zi1 = zv.y + 0.5f * dt * k1;
            } else if (stage == 1) {
                float2 a = *reinterpret_cast<const float2*>(&g_acc[idx]);
                *reinterpret_cast<float2*>(&g_acc[idx]) =
                    make_float2(a.x + 2.f * k0, a.y + 2.f * k1);
                zi0 = zv.x + 0.5f * dt * k0;
                zi1 = zv.y + 0.5f * dt * k1;
            } else if (stage == 2) {
                float2 a = *reinterpret_cast<const float2*>(&g_acc[idx]);
                *reinterpret_cast<float2*>(&g_acc[idx]) =
                    make_float2(a.x + 2.f * k0, a.y + 2.f * k1);
                zi0 = zv.x + dt * k0;
                zi1 = zv.y + dt * k1;
            } else {
                float2 a = *reinterpret_cast<const float2*>(&g_acc[idx]);
                zi0 = zv.x + (dt * (1.0f / 6.0f)) * (a.x + k0);
                zi1 = zv.y + (dt * (1.0f / 6.0f)) * (a.y + k1);
                *reinterpret_cast<float2*>(&g_z[idx]) = make_float2(zi0, zi1);
                *reinterpret_cast<float2*>(&traj[(size_t)(step + 1) * BB * DD + idx]) =
                    make_float2(zi0, zi1);
            }
            __nv_bfloat16 h0 = __float2bfloat16(zi0);
            __nv_bfloat16 h1 = __float2bfloat16(zi1);
            __nv_bfloat16 l0 = __float2bfloat16(zi0 - __bfloat162float(h0));
            __nv_bfloat16 l1 = __float2bfloat16(zi1 - __bfloat162float(h1));
            *reinterpret_cast<__nv_bfloat162*>(&g_zihi[idx]) = __halves2bfloat162(h0, h1);
            *reinterpret_cast<__nv_bfloat162*>(&g_zilo[idx]) = __halves2bfloat162(l0, l1);
        }
    }
}

// ---------------------------------------------------------------------------
// Setup kernels
// ---------------------------------------------------------------------------
__global__ void split_kernel(const float* __restrict__ src,
                             __nv_bfloat16* __restrict__ hi,
                             __nv_bfloat16* __restrict__ lo, int n) {
    int i = blockIdx.x * 256 + threadIdx.x;
    if (i < n) {
        float v = src[i];
        __nv_bfloat16 h = __float2bfloat16(v);
        hi[i] = h;
        lo[i] = __float2bfloat16(v - __bfloat162float(h));
    }
}

__global__ void init_kernel(const float* __restrict__ z0, float* __restrict__ traj) {
    int i = blockIdx.x * 256 + threadIdx.x;
    if (i < BB * DD) {
        float v = z0[i];
        g_z[i]  = v;
        traj[i] = v;
        __nv_bfloat16 h = __float2bfloat16(v);
        g_zihi[i] = h;
        g_zilo[i] = __float2bfloat16(v - __bfloat162float(h));
    }
}

// ---------------------------------------------------------------------------
extern "C" void kernel_launch(void* const* d_in, const int* in_sizes, int n_in,
                              void* d_out, int out_size) {
    const float* z0 = (const float*)d_in[0];
    const float* t  = (const float*)d_in[1];
    const float* W1 = (const float*)d_in[2];
    const float* b1 = (const float*)d_in[3];
    const float* W2 = (const float*)d_in[4];
    const float* b2 = (const float*)d_in[5];
    float* traj = (float*)d_out;

    __nv_bfloat16 *w1hi, *w1lo, *w2hi, *w2lo;
    cudaGetSymbolAddress((void**)&w1hi, g_W1hi);
    cudaGetSymbolAddress((void**)&w1lo, g_W1lo);
    cudaGetSymbolAddress((void**)&w2hi, g_W2hi);
    cudaGetSymbolAddress((void**)&w2lo, g_W2lo);

    cudaFuncSetAttribute(k_gemm1, cudaFuncAttributeMaxDynamicSharedMemorySize, SMEM_BYTES);
    cudaFuncSetAttribute(k_gemm2, cudaFuncAttributeMaxDynamicSharedMemorySize, SMEM_BYTES);

    split_kernel<<<(DD * HH + 255) / 256, 256>>>(W1, w1hi, w1lo, DD * HH);
    split_kernel<<<(HH * DD + 255) / 256, 256>>>(W2, w2hi, w2lo, HH * DD);
    init_kernel<<<(BB * DD + 255) / 256, 256>>>(z0, traj);

    dim3 thr(256);
    dim3 grid1(HH / 64, BB / 64);   // 16 x 16 = 256 CTAs
    dim3 grid2(DD / 64, BB / 64);   // 8  x 16 = 128 CTAs

    for (int step = 0; step < TT - 1; step++) {
        for (int s = 0; s < 4; s++) {
            k_gemm1<<<grid1, thr, SMEM_BYTES>>>(b1);
            k_gemm2<<<grid2, thr, SMEM_BYTES>>>(b2, t, step, s, traj);
        }
    }
}

// round 5
// speedup vs baseline: 4.6669x; 1.7189x over previous
#include <cuda_runtime.h>
#include <cuda_fp16.h>
#include <cstdint>

#define BB 1024   // batch
#define DD 512    // latent dim
#define HH 1024   // MLP hidden
#define TT 64     // time points

// ---------------------------------------------------------------------------
// Persistent device state (no allocs allowed).
// ---------------------------------------------------------------------------
__device__ __align__(16) float g_z  [BB * DD];   // current z (fp32)
__device__ __align__(16) float g_acc[BB * DD];   // k1 + 2k2 + 2k3
__device__ __align__(16) __half g_zin[BB * DD];  // stage input (fp16)
__device__ __align__(16) __half g_h  [BB * HH];  // hidden activation (fp16)
__device__ __align__(16) __half g_W1h[DD * HH];
__device__ __align__(16) __half g_W2h[HH * DD];

// ---------------------------------------------------------------------------
// PTX helpers
// ---------------------------------------------------------------------------
__device__ __forceinline__ void cpa16(void* dst, const void* src) {
    uint32_t d = (uint32_t)__cvta_generic_to_shared(dst);
    asm volatile("cp.async.cg.shared.global [%0], [%1], 16;\n" :: "r"(d), "l"(src));
}
__device__ __forceinline__ void cp_commit() {
    asm volatile("cp.async.commit_group;\n" ::: "memory");
}
template <int N>
__device__ __forceinline__ void cp_wait() {
    asm volatile("cp.async.wait_group %0;\n" :: "n"(N) : "memory");
}
__device__ __forceinline__ void ldsm4(uint32_t* r, const __half* p) {
    uint32_t a = (uint32_t)__cvta_generic_to_shared(p);
    asm volatile("ldmatrix.sync.aligned.m8n8.x4.shared.b16 {%0,%1,%2,%3},[%4];\n"
                 : "=r"(r[0]), "=r"(r[1]), "=r"(r[2]), "=r"(r[3]) : "r"(a));
}
__device__ __forceinline__ void ldsm4t(uint32_t* r, const __half* p) {
    uint32_t a = (uint32_t)__cvta_generic_to_shared(p);
    asm volatile("ldmatrix.sync.aligned.m8n8.x4.trans.shared.b16 {%0,%1,%2,%3},[%4];\n"
                 : "=r"(r[0]), "=r"(r[1]), "=r"(r[2]), "=r"(r[3]) : "r"(a));
}
__device__ __forceinline__ void mma_f16(float* c, const uint32_t* a, uint32_t b0, uint32_t b1) {
    asm volatile("mma.sync.aligned.m16n8k16.row.col.f32.f16.f16.f32 "
                 "{%0,%1,%2,%3}, {%4,%5,%6,%7}, {%8,%9}, {%0,%1,%2,%3};\n"
                 : "+f"(c[0]), "+f"(c[1]), "+f"(c[2]), "+f"(c[3])
                 : "r"(a[0]), "r"(a[1]), "r"(a[2]), "r"(a[3]), "r"(b0), "r"(b1));
}

// ---------------------------------------------------------------------------
// Mainloop: 64x64 CTA tile, BK=32, 128 threads, 4 warps (2x2), warp tile
// 32x32, single fp16 product, fp32 accumulate, 3-stage cp.async pipeline.
// A: [M,KDIM] row-major fp16.  B: [KDIM,NDIM] row-major fp16.
// ---------------------------------------------------------------------------
template <int KDIM, int NDIM>
__device__ __forceinline__ void mainloop(
    const __half* __restrict__ A, const __half* __restrict__ B,
    int m0, int n0, float c[2][4][4])
{
    __shared__ __align__(16) __half sA[3][64 * 40];   // [buf][m*40+k]
    __shared__ __align__(16) __half sB[3][32 * 72];   // [buf][k*72+n]

    const int tid  = threadIdx.x;
    const int wid  = tid >> 5;
    const int lane = tid & 31;
    const int wm = (wid >> 1) * 32;
    const int wn = (wid & 1) * 32;
    const int lr  = lane & 15;
    const int lc8 = (lane >> 4) * 8;

    auto load_tile = [&](int it, int b) {
        const int kk = it * 32;
#pragma unroll
        for (int j = 0; j < 2; j++) {
            int ch = tid + j * 128;                 // 0..255
            int r = ch >> 2, cA = (ch & 3) * 8;     // A: 64 rows x 4 chunks
            cpa16(&sA[b][r * 40 + cA], A + (size_t)(m0 + r) * KDIM + kk + cA);
            int rb = ch >> 3, cB = (ch & 7) * 8;    // B: 32 rows x 8 chunks
            cpa16(&sB[b][rb * 72 + cB], B + (size_t)(kk + rb) * NDIM + n0 + cB);
        }
        cp_commit();
    };

    auto compute = [&](int b) {
#pragma unroll
        for (int s = 0; s < 2; s++) {
            uint32_t av[2][4];
#pragma unroll
            for (int mt = 0; mt < 2; mt++)
                ldsm4(av[mt], &sA[b][(wm + mt * 16 + lr) * 40 + s * 16 + lc8]);
            uint32_t bv[2][4];
#pragma unroll
            for (int g = 0; g < 2; g++)
                ldsm4t(bv[g], &sB[b][(s * 16 + lr) * 72 + wn + g * 16 + lc8]);
#pragma unroll
            for (int mt = 0; mt < 2; mt++)
#pragma unroll
                for (int nt = 0; nt < 4; nt++) {
                    const int g = nt >> 1, w = (nt & 1) * 2;
                    mma_f16(c[mt][nt], av[mt], bv[g][w], bv[g][w + 1]);
                }
        }
    };

    constexpr int NT = KDIM / 32;
    load_tile(0, 0);
    load_tile(1, 1);
#pragma unroll 1
    for (int it = 0; it < NT; it++) {
        const int b = it % 3;
        cp_wait<1>();        // tile `it` resident (<=1 group pending)
        __syncthreads();     // all warps done with buffer (it+2)%3
        if (it + 2 < NT) load_tile(it + 2, (it + 2) % 3);
        compute(b);
    }
}

// ---------------------------------------------------------------------------
// GEMM1: h = tanh(zin @ W1 + b1) -> g_h (fp16)
// ---------------------------------------------------------------------------
__global__ void __launch_bounds__(128, 3) k_gemm1(const float* __restrict__ b1) {
    const int m0 = blockIdx.y * 64, n0 = blockIdx.x * 64;
    float c[2][4][4] = {};
    mainloop<DD, HH>(g_zin, g_W1h, m0, n0, c);

    const int wid = threadIdx.x >> 5, lane = threadIdx.x & 31;
    const int wm = (wid >> 1) * 32, wn = (wid & 1) * 32;
    const int er = lane >> 2, ec = (lane & 3) * 2;
#pragma unroll
    for (int mt = 0; mt < 2; mt++)
#pragma unroll
        for (int nt = 0; nt < 4; nt++) {
            int gn = n0 + wn + nt * 8 + ec;
            float bv0 = b1[gn], bv1 = b1[gn + 1];
#pragma unroll
            for (int h = 0; h < 2; h++) {
                int gm = m0 + wm + mt * 16 + er + h * 8;
                float v0 = tanhf(c[mt][nt][2 * h + 0] + bv0);
                float v1 = tanhf(c[mt][nt][2 * h + 1] + bv1);
                size_t idx = (size_t)gm * HH + gn;
                *reinterpret_cast<__half2*>(&g_h[idx]) =
                    __halves2half2(__float2half(v0), __float2half(v1));
            }
        }
}

// ---------------------------------------------------------------------------
// GEMM2 + RK4 combine: k = h @ W2 + b2, then stage update.
// ---------------------------------------------------------------------------
__global__ void __launch_bounds__(128, 3) k_gemm2(const float* __restrict__ b2,
                                                  const float* __restrict__ t,
                                                  int step, int stage,
                                                  float* __restrict__ traj) {
    const int m0 = blockIdx.y * 64, n0 = blockIdx.x * 64;
    float c[2][4][4] = {};
    mainloop<HH, DD>(g_h, g_W2h, m0, n0, c);

    const float dt = t[step + 1] - t[step];
    const int wid = threadIdx.x >> 5, lane = threadIdx.x & 31;
    const int wm = (wid >> 1) * 32, wn = (wid & 1) * 32;
    const int er = lane >> 2, ec = (lane & 3) * 2;

#pragma unroll
    for (int mt = 0; mt < 2; mt++)
#pragma unroll
        for (int nt = 0; nt < 4; nt++) {
            int gn = n0 + wn + nt * 8 + ec;
            float bv0 = b2[gn], bv1 = b2[gn + 1];
#pragma unroll
            for (int h = 0; h < 2; h++) {
                int gm = m0 + wm + mt * 16 + er + h * 8;
                int idx = gm * DD + gn;
                float k0 = c[mt][nt][2 * h + 0] + bv0;
                float k1 = c[mt][nt][2 * h + 1] + bv1;
                float2 zv = *reinterpret_cast<const float2*>(&g_z[idx]);
                float zi0, zi1;
                if (stage == 0) {
                    *reinterpret_cast<float2*>(&g_acc[idx]) = make_float2(k0, k1);
                    zi0 = zv.x + 0.5f * dt * k0;
                    zi1 = zv.y + 0.5f * dt * k1;
                } else if (stage == 1) {
                    float2 a = *reinterpret_cast<const float2*>(&g_acc[idx]);
                    *reinterpret_cast<float2*>(&g_acc[idx]) =
                        make_float2(a.x + 2.f * k0, a.y + 2.f * k1);
                    zi0 = zv.x + 0.5f * dt * k0;
                    zi1 = zv.y + 0.5f * dt * k1;
                } else if (stage == 2) {
                    float2 a = *reinterpret_cast<const float2*>(&g_acc[idx]);
                    *reinterpret_cast<float2*>(&g_acc[idx]) =
                        make_float2(a.x + 2.f * k0, a.y + 2.f * k1);
                    zi0 = zv.x + dt * k0;
                    zi1 = zv.y + dt * k1;
                } else {
                    float2 a = *reinterpret_cast<const float2*>(&g_acc[idx]);
                    zi0 = zv.x + (dt * (1.0f / 6.0f)) * (a.x + k0);
                    zi1 = zv.y + (dt * (1.0f / 6.0f)) * (a.y + k1);
                    *reinterpret_cast<float2*>(&g_z[idx]) = make_float2(zi0, zi1);
                    *reinterpret_cast<float2*>(&traj[(size_t)(step + 1) * BB * DD + idx]) =
                        make_float2(zi0, zi1);
                }
                *reinterpret_cast<__half2*>(&g_zin[idx]) =
                    __halves2half2(__float2half(zi0), __float2half(zi1));
            }
        }
}

// ---------------------------------------------------------------------------
// Setup kernels
// ---------------------------------------------------------------------------
__global__ void convert_kernel(const float* __restrict__ src,
                               __half* __restrict__ dst, int n) {
    int i = blockIdx.x * 256 + threadIdx.x;
    if (i < n) dst[i] = __float2half(src[i]);
}

__global__ void init_kernel(const float* __restrict__ z0, float* __restrict__ traj) {
    int i = blockIdx.x * 256 + threadIdx.x;
    if (i < BB * DD) {
        float v = z0[i];
        g_z[i]   = v;
        traj[i]  = v;
        g_zin[i] = __float2half(v);
    }
}

// ---------------------------------------------------------------------------
extern "C" void kernel_launch(void* const* d_in, const int* in_sizes, int n_in,
                              void* d_out, int out_size) {
    const float* z0 = (const float*)d_in[0];
    const float* t  = (const float*)d_in[1];
    const float* W1 = (const float*)d_in[2];
    const float* b1 = (const float*)d_in[3];
    const float* W2 = (const float*)d_in[4];
    const float* b2 = (const float*)d_in[5];
    float* traj = (float*)d_out;

    __half *w1h, *w2h;
    cudaGetSymbolAddress((void**)&w1h, g_W1h);
    cudaGetSymbolAddress((void**)&w2h, g_W2h);

    convert_kernel<<<(DD * HH + 255) / 256, 256>>>(W1, w1h, DD * HH);
    convert_kernel<<<(HH * DD + 255) / 256, 256>>>(W2, w2h, HH * DD);
    init_kernel<<<(BB * DD + 255) / 256, 256>>>(z0, traj);

    dim3 thr(128);
    dim3 grid1(HH / 64, BB / 64);   // 16 x 16 = 256 CTAs
    dim3 grid2(DD / 64, BB / 64);   // 8  x 16 = 128 CTAs

    for (int step = 0; step < TT - 1; step++) {
        for (int s = 0; s < 4; s++) {
            k_gemm1<<<grid1, thr>>>(b1);
            k_gemm2<<<grid2, thr>>>(b2, t, step, s, traj);
        }
    }
}